// round 16
// baseline (speedup 1.0000x reference)
#include <cuda_runtime.h>
#include <cuda_bf16.h>
#include <math.h>

#define NN 30000
#define EE 480000
#define HH 128
#define NLL 2
#define QLL 2
#define INV_NORM 0.01f

typedef unsigned long long u64;
typedef unsigned int u32;

// ---------------- device scratch (static, no allocation) ----------------
__device__ float  g_radial[EE];
__device__ float  g_cdiff[EE * 3];
__device__ float  g_agg[NN * HH];
__device__ __align__(16) __nv_bfloat16 g_hb[NN * HH];   // bf16 mirror of h
__device__ float2 g_aug[NLL * QLL * 128 * 256];
__device__ float2 g_xb[NLL * QLL * 128 * 128];
__device__ float2 g_gk[NLL * QLL * 128 * 128];
__device__ float2 g_qm[NLL * QLL * 128 * 128];
__device__ float2 g_bp[NLL * QLL * 128 * 128];
__device__ float2 g_ml[NLL * 128 * 128];
__device__ int    g_perm[128];
__device__ __align__(16) __nv_bfloat16 g_w1t[NLL * 128 * 256];
__device__ __align__(16) __nv_bfloat16 g_w2t[NLL * 128 * 128];
__device__ __align__(16) __nv_bfloat16 g_cw1t[128 * 256];
__device__ __align__(16) __nv_bfloat16 g_cw2t[128 * 128];
__device__ __align__(16) __nv_bfloat16 g_encth[NLL * 128 * 256];
__device__ __align__(16) __nv_bfloat16 g_enctl[NLL * 128 * 256];
__device__ __align__(16) __nv_bfloat16 g_wrth[NLL * 128 * 128];
__device__ __align__(16) __nv_bfloat16 g_wrtl[NLL * 128 * 128];

__device__ __forceinline__ float2 cmulf(float2 a, float2 b) {
    return make_float2(a.x * b.x - a.y * b.y, a.x * b.y + a.y * b.x);
}
__device__ __forceinline__ float siluf(float v) {
    float t;
    asm("tanh.approx.f32 %0, %1;" : "=f"(t) : "f"(0.5f * v));
    return 0.5f * v * (1.f + t);
}

__device__ __forceinline__ void red_add_v4(float* p, float a, float b, float c, float d) {
    asm volatile("red.global.add.v4.f32 [%0], {%1, %2, %3, %4};"
                 :: "l"(p), "f"(a), "f"(b), "f"(c), "f"(d) : "memory");
}
__device__ __forceinline__ u32 bf2(float lo, float hi) {
    u32 r; asm("cvt.rn.bf16x2.f32 %0, %1, %2;" : "=r"(r) : "f"(hi), "f"(lo)); return r;
}
__device__ __forceinline__ u32 smem_u32(const void* p) {
    u32 a; asm("{ .reg .u64 t; cvta.to.shared.u64 t, %1; cvt.u32.u64 %0, t; }"
               : "=r"(a) : "l"(p));
    return a;
}
#define STS128(addr, a, b, c, d) \
    asm volatile("st.shared.v4.b32 [%0], {%1, %2, %3, %4};" \
                 :: "r"(addr), "r"(a), "r"(b), "r"(c), "r"(d) : "memory")
#define STS32(addr, a) \
    asm volatile("st.shared.b32 [%0], %1;" :: "r"(addr), "r"(a) : "memory")
#define CP_ASYNC16(dst, src) \
    asm volatile("cp.async.ca.shared.global [%0], [%1], 16;" :: "r"(dst), "l"(src) : "memory")
#define CP_COMMIT() asm volatile("cp.async.commit_group;" ::: "memory")
#define CP_WAIT0()  asm volatile("cp.async.wait_group 0;" ::: "memory")

// ---------------- portable tensor-core primitives ----------
__device__ __forceinline__ void ldsm4(u32& r0, u32& r1, u32& r2, u32& r3, u32 addr) {
    asm volatile("ldmatrix.sync.aligned.m8n8.x4.shared.b16 {%0,%1,%2,%3}, [%4];"
                 : "=r"(r0), "=r"(r1), "=r"(r2), "=r"(r3) : "r"(addr));
}
__device__ __forceinline__ void mma16816(float* d, u32 a0, u32 a1, u32 a2, u32 a3,
                                         u32 b0, u32 b1) {
    asm volatile(
        "mma.sync.aligned.m16n8k16.row.col.f32.bf16.bf16.f32 "
        "{%0,%1,%2,%3}, {%4,%5,%6,%7}, {%8,%9}, {%0,%1,%2,%3};"
        : "+f"(d[0]), "+f"(d[1]), "+f"(d[2]), "+f"(d[3])
        : "r"(a0), "r"(a1), "r"(a2), "r"(a3), "r"(b0), "r"(b1));
}

template <int K>
__device__ __forceinline__ u32 swz(int r, int k) {
    return (u32)(r * (K * 2) + ((((k >> 3) ^ (r & 7)) << 4) | ((k & 7) << 1)));
}

// ---- 256-thread full-width GEMM (node kernel) ----
template <int K>
__device__ __forceinline__ void mma_gemm(u32 sbA, u32 sbB, int warp, int lane,
                                         float d[16][4]) {
    int arow = warp * 16 + (lane & 15);
    int akoff = (lane >> 4) << 3;
    int brow = (lane & 7) + ((lane & 16) >> 1);
    int bkoff = (lane & 8);
#pragma unroll
    for (int ks = 0; ks < K / 16; ks++) {
        int k0 = ks * 16;
        u32 a0, a1, a2, a3;
        ldsm4(a0, a1, a2, a3, sbA + swz<K>(arow, k0 + akoff));
#pragma unroll
        for (int u = 0; u < 8; u++) {
            u32 b0, b1, b2, b3;
            ldsm4(b0, b1, b2, b3, sbB + swz<K>(16 * u + brow, k0 + bkoff));
            mma16816(d[2 * u], a0, a1, a2, a3, b0, b1);
            mma16816(d[2 * u + 1], a0, a1, a2, a3, b2, b3);
        }
    }
}
__device__ __forceinline__ void zero_d(float d[16][4]) {
#pragma unroll
    for (int i = 0; i < 16; i++)
#pragma unroll
        for (int j = 0; j < 4; j++) d[i][j] = 0.f;
}

// ---- 512-thread quad-tile GEMM (edge kernels): warp (rg, nh) covers
// rows [32rg, 32rg+32) x cols [32nh, 32nh+32)
template <int K>
__device__ __forceinline__ void mma_gemm_q(u32 sbA, u32 sbB, int rg, int nh,
                                           int lane, float d[8][4]) {
    int arow = rg * 32 + (lane & 15);
    int akoff = (lane >> 4) << 3;
    int brow = nh * 32 + (lane & 7) + ((lane & 16) >> 1);
    int bkoff = (lane & 8);
#pragma unroll
    for (int ks = 0; ks < K / 16; ks++) {
        int k0 = ks * 16;
        u32 a[2][4], b[2][4];
        ldsm4(a[0][0], a[0][1], a[0][2], a[0][3], sbA + swz<K>(arow, k0 + akoff));
        ldsm4(a[1][0], a[1][1], a[1][2], a[1][3], sbA + swz<K>(arow + 16, k0 + akoff));
        ldsm4(b[0][0], b[0][1], b[0][2], b[0][3], sbB + swz<K>(brow, k0 + bkoff));
        ldsm4(b[1][0], b[1][1], b[1][2], b[1][3], sbB + swz<K>(brow + 16, k0 + bkoff));
#pragma unroll
        for (int ai = 0; ai < 2; ai++)
#pragma unroll
            for (int bj = 0; bj < 2; bj++) {
                mma16816(d[ai * 4 + bj * 2 + 0], a[ai][0], a[ai][1], a[ai][2], a[ai][3],
                         b[bj][0], b[bj][1]);
                mma16816(d[ai * 4 + bj * 2 + 1], a[ai][0], a[ai][1], a[ai][2], a[ai][3],
                         b[bj][2], b[bj][3]);
            }
    }
}
__device__ __forceinline__ void zero_d8(float d[8][4]) {
#pragma unroll
    for (int i = 0; i < 8; i++)
#pragma unroll
        for (int j = 0; j < 4; j++) d[i][j] = 0.f;
}

// ---------------- merged init ----------------
#define C_COPY (NN * HH)
#define C_GEO  EE
#define C_AUG  (NLL * QLL * 128 * 256)
#define C_GK   (NLL * QLL * 128 * 128)
#define C_W1T  (NLL * 128 * 256)
#define C_W2T  (NLL * 128 * 128)
#define C_CW1  (128 * 256)
#define C_CW2  (128 * 128)
#define C_ENC  (NLL * 128 * 256)
#define C_TOT  (C_COPY + C_GEO + C_AUG + C_GK + C_W1T + C_W2T + C_CW1 + C_CW2 + C_ENC + 1)

__global__ void k_init(const float* __restrict__ h0, const float* __restrict__ x0,
                       float* __restrict__ out, const int* __restrict__ ei,
                       const float* __restrict__ Are, const float* __restrict__ Aim,
                       const float* __restrict__ coeffs, const float* __restrict__ e_w1,
                       const float* __restrict__ e_w2, const float* __restrict__ c_w1,
                       const float* __restrict__ c_w2, const float* __restrict__ enc_w) {
    int idx = blockIdx.x * 256 + threadIdx.x;
    if (idx < C_COPY) {
        float v = h0[idx];
        out[idx] = v;
        g_hb[idx] = __float2bfloat16(v);
        if (idx < NN * 3) out[C_COPY + idx] = x0[idx];
        return;
    }
    idx -= C_COPY;
    if (idx < C_GEO) {
        int e = idx;
        int r = ei[e], c = ei[EE + e];
        float dx = x0[r * 3 + 0] - x0[c * 3 + 0];
        float dy = x0[r * 3 + 1] - x0[c * 3 + 1];
        float dz = x0[r * 3 + 2] - x0[c * 3 + 2];
        float rad = dx * dx + dy * dy + dz * dz;
        g_radial[e] = rad;
        float s = 1.f / (sqrtf(rad + 1e-8f) + 1.0f);
        g_cdiff[e * 3 + 0] = dx * s;
        g_cdiff[e * 3 + 1] = dy * s;
        g_cdiff[e * 3 + 2] = dz * s;
        return;
    }
    idx -= C_GEO;
    if (idx < C_AUG) {
        int mat = idx >> 15;
        int rem = idx & 32767;
        int i = rem >> 8, c = rem & 255;
        const float* Ar = Are + mat * 16384;
        const float* Ai = Aim + mat * 16384;
        float2 v;
        if (c < 128) {
            v.x = Ar[i * 128 + c] + Ar[c * 128 + i];
            v.y = Ai[i * 128 + c] - Ai[c * 128 + i] + (i == c ? 1.f : 0.f);
        } else {
            int cc = c - 128;
            v.x = Ar[i * 128 + cc] + Ar[cc * 128 + i];
            v.y = Ai[i * 128 + cc] - Ai[cc * 128 + i] - (i == cc ? 1.f : 0.f);
        }
        g_aug[idx] = v;
        return;
    }
    idx -= C_AUG;
    if (idx < C_GK) {
        int mat = idx >> 14;
        int rem = idx & 16383;
        int r = rem >> 7, c = rem & 127;
        float a = coeffs[mat * 2 + 0], b = coeffs[mat * 2 + 1];
        float ca = cosf(0.5f * a), sa = sinf(0.5f * a);
        float cb = cosf(0.5f * b), sb = sinf(0.5f * b);
        float2 G[2][2];
        G[0][0] = make_float2(cb * ca, sb * sa);
        G[0][1] = make_float2(-sb * ca, -cb * sa);
        G[1][0] = make_float2(sb * ca, -cb * sa);
        G[1][1] = make_float2(cb * ca, -sb * sa);
        float2 p = G[(r >> 6) & 1][(c >> 6) & 1];
#pragma unroll
        for (int t = 5; t >= 0; t--) p = cmulf(p, G[(r >> t) & 1][(c >> t) & 1]);
        g_gk[idx] = p;
        return;
    }
    idx -= C_GK;
    if (idx < C_W1T) {
        int l = idx / (128 * 256);
        int rem = idx - l * 128 * 256;
        int n = rem >> 8, k = rem & 255;
        g_w1t[idx] = __float2bfloat16(e_w1[(l * 258 + k) * 128 + n]);
        return;
    }
    idx -= C_W1T;
    if (idx < C_W2T) {
        int l = idx >> 14;
        int rem = idx & 16383;
        int n = rem >> 7, k = rem & 127;
        g_w2t[idx] = __float2bfloat16(e_w2[(l * 128 + k) * 128 + n]);
        return;
    }
    idx -= C_W2T;
    if (idx < C_CW1) {
        int n = idx >> 8, k = idx & 255;
        g_cw1t[idx] = __float2bfloat16(c_w1[k * 128 + n]);
        return;
    }
    idx -= C_CW1;
    if (idx < C_CW2) {
        int n = idx >> 7, k = idx & 127;
        g_cw2t[idx] = __float2bfloat16(c_w2[k * 128 + n]);
        return;
    }
    idx -= C_CW2;
    if (idx < C_ENC) {
        int l = idx >> 15;
        int rem = idx & 32767;
        int n = rem >> 8, k = rem & 255;
        float x = enc_w[(l * 256 + k) * 128 + n];
        __nv_bfloat16 hb = __float2bfloat16(x);
        float lo = x - __bfloat162float(hb);
        g_encth[l * 32768 + n * 256 + k] = hb;
        g_enctl[l * 32768 + n * 256 + k] = __float2bfloat16(lo);
        return;
    }
    idx -= C_ENC;
    if (idx == 0) {
        int g[128], tmp[128];
        bool first = true;
        for (int p = 0; p < 7; p++) {
            int c = (p < 6) ? p : 6;
            int t = (p < 6) ? p + 1 : 0;
            for (int i = 0; i < 128; i++) {
                int cb = (i >> (6 - c)) & 1;
                int f = i ^ (cb << (6 - t));
                tmp[i] = first ? f : g[f];
            }
            for (int i = 0; i < 128; i++) g[i] = tmp[i];
            first = false;
        }
        for (int i = 0; i < 128; i++) g_perm[i] = g[i];
    }
}

// ---------------- Newton inverse (chip-wide grids) ----------------
__global__ void k_nt(const float2* __restrict__ X, int mstride, int rstride) {
    int g = blockIdx.x * 256 + threadIdx.x;
    int mat = g >> 14;
    int e = g & 16383;
    int i = e >> 7, j = e & 127;
    const float2* M = g_aug + mat * 32768;
    const float2* Xm = X + mat * mstride;
    float2 acc = make_float2(0.f, 0.f);
#pragma unroll 4
    for (int k = 0; k < 128; k++) {
        float2 m = M[i * 256 + k];
        float2 x = Xm[k * rstride + j];
        acc.x += m.x * x.x - m.y * x.y;
        acc.y += m.x * x.y + m.y * x.x;
    }
    g_bp[g] = acc;
}

__global__ void k_nx(const float2* __restrict__ X, int mstride, int rstride,
                     float2* __restrict__ Xo, int omstride, int orstride) {
    int g = blockIdx.x * 256 + threadIdx.x;
    int mat = g >> 14;
    int e = g & 16383;
    int i = e >> 7, j = e & 127;
    const float2* Xm = X + mat * mstride;
    const float2* Tm = g_bp + mat * 16384;
    float2 xij = Xm[i * rstride + j];
    float2 acc = make_float2(2.f * xij.x, 2.f * xij.y);
#pragma unroll 4
    for (int k = 0; k < 128; k++) {
        float2 x = Xm[i * rstride + k];
        float2 t = Tm[k * 128 + j];
        acc.x -= x.x * t.x - x.y * t.y;
        acc.y -= x.x * t.y + x.y * t.x;
    }
    Xo[mat * omstride + i * orstride + j] = acc;
}

__global__ void k_q(const float* __restrict__ Are, const float* __restrict__ Aim,
                    const float2* __restrict__ X, int mstride, int rstride) {
    int g = blockIdx.x * 256 + threadIdx.x;
    int mat = g >> 14;
    int e = g & 16383;
    int i = e >> 7, j = e & 127;
    const float* Ar = Are + mat * 16384;
    const float* Ai = Aim + mat * 16384;
    const float2* Xm = X + mat * mstride;
    float2 acc = make_float2(0.f, 0.f);
#pragma unroll 4
    for (int k = 0; k < 128; k++) {
        float2 mm = make_float2(Ar[i * 128 + k] + Ar[k * 128 + i],
                                Ai[i * 128 + k] - Ai[k * 128 + i] - (i == k ? 1.f : 0.f));
        float2 pv = Xm[k * rstride + j];
        acc.x += mm.x * pv.x - mm.y * pv.y;
        acc.y += mm.x * pv.y + mm.y * pv.x;
    }
    g_qm[g] = acc;
}

__global__ void k_b() {
    int g = blockIdx.x * 256 + threadIdx.x;
    int mat = g >> 14;
    int e = g & 16383;
    int i = e >> 7, k = e & 127;
    const float2* Q = g_qm + mat * 16384;
    const float2* Gk = g_gk + mat * 16384 + g_perm[k] * 128;
    float2 acc = make_float2(0.f, 0.f);
#pragma unroll 4
    for (int m = 0; m < 128; m++) {
        float2 q = Q[m * 128 + i];
        float2 gk = Gk[m];
        acc.x += q.x * gk.x - q.y * gk.y;
        acc.y += q.x * gk.y + q.y * gk.x;
    }
    g_bp[g] = acc;
}

__global__ void k_m() {
    int g = blockIdx.x * 256 + threadIdx.x;
    int l = g >> 14;
    int e = g & 16383;
    int i = e >> 7, j = e & 127;
    const float2* B0 = g_bp + (2 * l) * 16384;
    const float2* B1 = g_bp + (2 * l + 1) * 16384;
    float2 acc = make_float2(0.f, 0.f);
#pragma unroll 4
    for (int k = 0; k < 128; k++) {
        float2 a = B0[i * 128 + k];
        float2 b = B1[k * 128 + j];
        acc.x += a.x * b.x - a.y * b.y;
        acc.y += a.x * b.y + a.y * b.x;
    }
    g_ml[g] = acc;
}

__global__ void k_w(const float* __restrict__ decW) {
    int g = blockIdx.x * 256 + threadIdx.x;
    int l = g >> 14;
    int e = g & 16383;
    int k = e >> 7, n = e & 127;
    const float2* M = g_ml + l * 16384 + k * 128;
    const float* W = decW + l * 16384;
    float acc = 0.f;
#pragma unroll 4
    for (int m = 0; m < 128; m++) acc += M[m].x * W[m * 128 + n];
    __nv_bfloat16 hb = __float2bfloat16(acc);
    float lo = acc - __bfloat162float(hb);
    g_wrth[l * 16384 + n * 128 + k] = hb;
    g_wrtl[l * 16384 + n * 128 + k] = __float2bfloat16(lo);
}

__global__ void k_zero_agg() {
    int i = blockIdx.x * blockDim.x + threadIdx.x;
    if (i < NN * HH) g_agg[i] = 0.f;
}

// ================= staging helpers =================
__device__ __forceinline__ void stage_w1(const __nv_bfloat16* __restrict__ src,
                                         u32 dst, int tid) {
    int lane = tid & 31, wy = tid >> 5;
    for (int it = 0; it < 16; it++) {
        int n = wy + 8 * it;
        int k0 = lane * 8;
        uint4 v = *(const uint4*)(src + n * 256 + k0);
        STS128(dst + swz<256>(n, k0), v.x, v.y, v.z, v.w);
    }
}
__device__ __forceinline__ void stage_w2(const __nv_bfloat16* __restrict__ src,
                                         u32 dst, int tid) {
    int lane = tid & 31, wy = tid >> 5;
    if (lane < 16) {
        for (int it = 0; it < 16; it++) {
            int n = wy + 8 * it;
            int k0 = lane * 8;
            uint4 v = *(const uint4*)(src + n * 128 + k0);
            STS128(dst + swz<128>(n, k0), v.x, v.y, v.z, v.w);
        }
    }
}
__device__ __forceinline__ void stage_w1_512(const __nv_bfloat16* __restrict__ src,
                                             u32 dst, int tid) {
    int lane = tid & 31, wy = tid >> 5;
    for (int it = 0; it < 8; it++) {
        int n = wy + 16 * it;
        int k0 = lane * 8;
        uint4 v = *(const uint4*)(src + n * 256 + k0);
        STS128(dst + swz<256>(n, k0), v.x, v.y, v.z, v.w);
    }
}
__device__ __forceinline__ void stage_w2_512(const __nv_bfloat16* __restrict__ src,
                                             u32 dst, int tid) {
    int lane = tid & 31, wy = tid >> 5;
    if (lane < 16) {
        for (int it = 0; it < 8; it++) {
            int n = wy + 16 * it;
            int k0 = lane * 8;
            uint4 v = *(const uint4*)(src + n * 128 + k0);
            STS128(dst + swz<128>(n, k0), v.x, v.y, v.z, v.w);
        }
    }
}

// ================= mma.sync edge kernels (512 threads, 32x32 tiles) ============
#define OFF_RIDX 0
#define OFF_RS   512
#define OFF_ES   1024
#define OFF_B1S  1536
#define OFF_B2S  2048
#define OFF_WR0  2560
#define OFF_WR1  3072
#define OFF_W3S  3584
#define OFF_TSUM 4096
#define OFF_A1   8192
#define OFF_W1S  (OFF_A1 + 65536)
#define OFF_A2   (OFF_W1S + 65536)
#define OFF_W2S  (OFF_A2 + 32768)
#define SMEM_TC  (OFF_W2S + 32768)
#define NTILES   (EE / 128)
#define TCGRID   148

// cp.async gather from bf16 h mirror
__device__ __forceinline__ void gather_tile(const int* __restrict__ ei,
                                            const float* __restrict__ eattr,
                                            u32 sb, float* smf, int* smi,
                                            int e0, int tid) {
    int lane = tid & 31, wy = tid >> 5;
    for (int it = 0; it < 8; it++) {
        int m = wy + 16 * it;
        int e = e0 + m;
        int r = ei[e], c = ei[EE + e];
        if (lane == 0) {
            smi[OFF_RIDX / 4 + m] = r;
            smf[OFF_RS / 4 + m] = g_radial[e];
            smf[OFF_ES / 4 + m] = eattr[e];
        }
        int src = (lane < 16) ? r : c;
        int koff = (lane & 15) * 8;
        const __nv_bfloat16* sp = g_hb + src * 128 + koff;
        u32 dst = sb + OFF_A1 + swz<256>(m, lane * 8);
        CP_ASYNC16(dst, sp);
    }
    CP_COMMIT();
    CP_WAIT0();
}

__device__ __forceinline__ void epi1_q(float d[8][4], const float* smf, u32 sb,
                                       int rg, int nh, int lane) {
#pragma unroll
    for (int ai = 0; ai < 2; ai++) {
        int r0 = rg * 32 + ai * 16 + (lane >> 2);
        int r1 = r0 + 8;
        float rad0 = smf[OFF_RS / 4 + r0], ea0 = smf[OFF_ES / 4 + r0];
        float rad1 = smf[OFF_RS / 4 + r1], ea1 = smf[OFF_ES / 4 + r1];
#pragma unroll
        for (int bj = 0; bj < 2; bj++)
#pragma unroll
            for (int nt2 = 0; nt2 < 2; nt2++) {
                int idx = ai * 4 + bj * 2 + nt2;
                int c0 = nh * 32 + bj * 16 + nt2 * 8 + 2 * (lane & 3);
                float b1a = smf[OFF_B1S / 4 + c0], b1b = smf[OFF_B1S / 4 + c0 + 1];
                float w0a = smf[OFF_WR0 / 4 + c0], w0b = smf[OFF_WR0 / 4 + c0 + 1];
                float w1a = smf[OFF_WR1 / 4 + c0], w1b = smf[OFF_WR1 / 4 + c0 + 1];
                float v0 = siluf(d[idx][0] + b1a + rad0 * w0a + ea0 * w1a);
                float v1 = siluf(d[idx][1] + b1b + rad0 * w0b + ea0 * w1b);
                float v2 = siluf(d[idx][2] + b1a + rad1 * w0a + ea1 * w1a);
                float v3 = siluf(d[idx][3] + b1b + rad1 * w0b + ea1 * w1b);
                STS32(sb + OFF_A2 + swz<128>(r0, c0), bf2(v0, v1));
                STS32(sb + OFF_A2 + swz<128>(r1, c0), bf2(v2, v3));
            }
    }
}

__global__ void __launch_bounds__(512, 1) k_edge_msg(
    const int* __restrict__ ei, const float* __restrict__ eattr,
    const float* __restrict__ w1f, const float* __restrict__ b1,
    const float* __restrict__ b2, int l) {
    extern __shared__ char sm[];
    u32 sb = smem_u32(sm);
    float* smf = (float*)sm;
    int* smi = (int*)sm;
    int tid = threadIdx.x;
    int warp = tid >> 5, lane = tid & 31;
    int rg = warp & 3, nh = warp >> 2;

    stage_w1_512(g_w1t + l * 128 * 256, sb + OFF_W1S, tid);
    stage_w2_512(g_w2t + l * 128 * 128, sb + OFF_W2S, tid);
    if (tid < 128) {
        smf[OFF_B1S / 4 + tid] = b1[tid];
        smf[OFF_B2S / 4 + tid] = b2[tid];
        smf[OFF_WR0 / 4 + tid] = w1f[256 * 128 + tid];
        smf[OFF_WR1 / 4 + tid] = w1f[257 * 128 + tid];
    }
    __syncthreads();

    float d[8][4];
    for (int t = blockIdx.x; t < NTILES; t += TCGRID) {
        gather_tile(ei, eattr, sb, smf, smi, t * 128, tid);
        __syncthreads();
        zero_d8(d);
        mma_gemm_q<256>(sb + OFF_A1, sb + OFF_W1S, rg, nh, lane, d);
        epi1_q(d, smf, sb, rg, nh, lane);
        __syncthreads();
        zero_d8(d);
        mma_gemm_q<128>(sb + OFF_A2, sb + OFF_W2S, rg, nh, lane, d);
#pragma unroll
        for (int ai = 0; ai < 2; ai++) {
            int r0 = rg * 32 + ai * 16 + (lane >> 2);
            int r1 = r0 + 8;
            int row0 = smi[OFF_RIDX / 4 + r0];
            int row1 = smi[OFF_RIDX / 4 + r1];
#pragma unroll
            for (int bj = 0; bj < 2; bj++)
#pragma unroll
                for (int nt2 = 0; nt2 < 2; nt2++) {
                    int idx = ai * 4 + bj * 2 + nt2;
                    int c0 = nh * 32 + bj * 16 + nt2 * 8 + 2 * (lane & 3);
                    int cbase = nh * 32 + bj * 16 + nt2 * 8 + ((lane & 2) << 1);
                    float b2a = smf[OFF_B2S / 4 + c0], b2b = smf[OFF_B2S / 4 + c0 + 1];
                    float a0 = siluf(d[idx][0] + b2a) * INV_NORM;
                    float a1 = siluf(d[idx][1] + b2b) * INV_NORM;
                    float a2 = siluf(d[idx][2] + b2a) * INV_NORM;
                    float a3 = siluf(d[idx][3] + b2b) * INV_NORM;
                    float p0 = __shfl_xor_sync(0xffffffffu, a0, 1);
                    float p1 = __shfl_xor_sync(0xffffffffu, a1, 1);
                    float p2 = __shfl_xor_sync(0xffffffffu, a2, 1);
                    float p3 = __shfl_xor_sync(0xffffffffu, a3, 1);
                    if (!(lane & 1)) {
                        red_add_v4(g_agg + row0 * HH + cbase, a0, a1, p0, p1);
                        red_add_v4(g_agg + row1 * HH + cbase, a2, a3, p2, p3);
                    }
                }
        }
        __syncthreads();
    }
}

__global__ void __launch_bounds__(512, 1) k_edge_final(
    const int* __restrict__ ei, const float* __restrict__ eattr,
    const float* __restrict__ cw1f, const float* __restrict__ cb1,
    const float* __restrict__ cb2, const float* __restrict__ cw3,
    float* __restrict__ xout) {
    extern __shared__ char sm[];
    u32 sb = smem_u32(sm);
    float* smf = (float*)sm;
    int* smi = (int*)sm;
    int tid = threadIdx.x;
    int warp = tid >> 5, lane = tid & 31;
    int rg = warp & 3, nh = warp >> 2;

    stage_w1_512(g_cw1t, sb + OFF_W1S, tid);
    stage_w2_512(g_cw2t, sb + OFF_W2S, tid);
    if (tid < 128) {
        smf[OFF_B1S / 4 + tid] = cb1[tid];
        smf[OFF_B2S / 4 + tid] = cb2[tid];
        smf[OFF_WR0 / 4 + tid] = cw1f[256 * 128 + tid];
        smf[OFF_WR1 / 4 + tid] = cw1f[257 * 128 + tid];
        smf[OFF_W3S / 4 + tid] = cw3[tid];
    }
    __syncthreads();

    float d[8][4];
    for (int t = blockIdx.x; t < NTILES; t += TCGRID) {
        int e0 = t * 128;
        gather_tile(ei, eattr, sb, smf, smi, e0, tid);
        __syncthreads();
        zero_d8(d);
        mma_gemm_q<256>(sb + OFF_A1, sb + OFF_W1S, rg, nh, lane, d);
        epi1_q(d, smf, sb, rg, nh, lane);
        __syncthreads();
        zero_d8(d);
        mma_gemm_q<128>(sb + OFF_A2, sb + OFF_W2S, rg, nh, lane, d);
#pragma unroll
        for (int ai = 0; ai < 2; ai++) {
            int r0 = rg * 32 + ai * 16 + (lane >> 2);
            int r1 = r0 + 8;
            float t0 = 0.f, t1 = 0.f;
#pragma unroll
            for (int bj = 0; bj < 2; bj++)
#pragma unroll
                for (int nt2 = 0; nt2 < 2; nt2++) {
                    int idx = ai * 4 + bj * 2 + nt2;
                    int c0 = nh * 32 + bj * 16 + nt2 * 8 + 2 * (lane & 3);
                    float b2a = smf[OFF_B2S / 4 + c0], b2b = smf[OFF_B2S / 4 + c0 + 1];
                    float w3a = smf[OFF_W3S / 4 + c0], w3b = smf[OFF_W3S / 4 + c0 + 1];
                    t0 += siluf(d[idx][0] + b2a) * w3a + siluf(d[idx][1] + b2b) * w3b;
                    t1 += siluf(d[idx][2] + b2a) * w3a + siluf(d[idx][3] + b2b) * w3b;
                }
            t0 += __shfl_xor_sync(0xffffffffu, t0, 1);
            t0 += __shfl_xor_sync(0xffffffffu, t0, 2);
            t1 += __shfl_xor_sync(0xffffffffu, t1, 1);
            t1 += __shfl_xor_sync(0xffffffffu, t1, 2);
            if (!(lane & 3)) {
                smf[OFF_TSUM / 4 + nh * 128 + r0] = t0;
                smf[OFF_TSUM / 4 + nh * 128 + r1] = t1;
            }
        }
        __syncthreads();
        if (tid < 128) {
            int e = e0 + tid;
            int r = smi[OFF_RIDX / 4 + tid];
            float tt = (smf[OFF_TSUM / 4 + tid] + smf[OFF_TSUM / 4 + 128 + tid] +
                        smf[OFF_TSUM / 4 + 256 + tid] + smf[OFF_TSUM / 4 + 384 + tid]) *
                       INV_NORM;
            atomicAdd(&xout[r * 3 + 0], g_cdiff[e * 3 + 0] * tt);
            atomicAdd(&xout[r * 3 + 1], g_cdiff[e * 3 + 1] * tt);
            atomicAdd(&xout[r * 3 + 2], g_cdiff[e * 3 + 2] * tt);
        }
        __syncthreads();
    }
}

// ================= node kernel (256 threads, split-bf16) =========
#define OFF_AH 4096
#define OFF_AL (OFF_AH + 65536)
#define OFF_WB (OFF_AL + 65536)
#define SMEM_ND (OFF_WB + 65536)

__device__ __forceinline__ void gather_node(const float* __restrict__ h, int n0,
                                            u32 sb, int tid) {
    int lane = tid & 31, wy = tid >> 5;
    for (int it = 0; it < 16; it++) {
        int m = wy + 8 * it;
        int n = n0 + m;
        float4 v0 = make_float4(0.f, 0.f, 0.f, 0.f), v1 = v0;
        if (n < NN) {
            const float* base = (lane < 16) ? (h + n * 128 + lane * 8)
                                            : (g_agg + n * 128 + lane * 8 - 128);
            v0 = ((const float4*)base)[0];
            v1 = ((const float4*)base)[1];
        }
        float a[8] = {v0.x, v0.y, v0.z, v0.w, v1.x, v1.y, v1.z, v1.w};
        u32 hp[4], lp[4];
#pragma unroll
        for (int q = 0; q < 4; q++) {
            float f0 = a[2 * q], f1 = a[2 * q + 1];
            float g0 = __bfloat162float(__float2bfloat16(f0));
            float g1 = __bfloat162float(__float2bfloat16(f1));
            hp[q] = bf2(g0, g1);
            lp[q] = bf2(f0 - g0, f1 - g1);
        }
        u32 off = swz<256>(m, lane * 8);
        STS128(sb + OFF_AH + off, hp[0], hp[1], hp[2], hp[3]);
        STS128(sb + OFF_AL + off, lp[0], lp[1], lp[2], lp[3]);
    }
}

__global__ void __launch_bounds__(256, 1) k_node(
    float* __restrict__ h, const float* __restrict__ encB, int l,
    const float* __restrict__ decB) {
    extern __shared__ char sm[];
    u32 sb = smem_u32(sm);
    float* smf = (float*)sm;
    int tid = threadIdx.x;
    int warp = tid >> 5, lane = tid & 31;
    int n0 = blockIdx.x * 128;

    if (tid < 128) {
        smf[tid] = encB[tid];
        smf[128 + tid] = decB[tid];
    }
    gather_node(h, n0, sb, tid);
    stage_w1(g_encth + l * 32768, sb + OFF_WB, tid);
    __syncthreads();

    float d[16][4];
    zero_d(d);
    mma_gemm<256>(sb + OFF_AH, sb + OFF_WB, warp, lane, d);
    mma_gemm<256>(sb + OFF_AL, sb + OFF_WB, warp, lane, d);
    __syncthreads();
    stage_w1(g_enctl + l * 32768, sb + OFF_WB, tid);
    __syncthreads();
    mma_gemm<256>(sb + OFF_AH, sb + OFF_WB, warp, lane, d);

    int r0 = warp * 16 + (lane >> 2);
    int r1 = r0 + 8;
    float s0 = 0.f, s1 = 0.f;
#pragma unroll
    for (int nt = 0; nt < 16; nt++) {
        int c0 = nt * 8 + 2 * (lane & 3);
        float ba = smf[c0], bb = smf[c0 + 1];
        d[nt][0] += ba; d[nt][1] += bb; d[nt][2] += ba; d[nt][3] += bb;
        s0 += d[nt][0] * d[nt][0] + d[nt][1] * d[nt][1];
        s1 += d[nt][2] * d[nt][2] + d[nt][3] * d[nt][3];
    }
    s0 += __shfl_xor_sync(0xffffffffu, s0, 1);
    s0 += __shfl_xor_sync(0xffffffffu, s0, 2);
    s1 += __shfl_xor_sync(0xffffffffu, s1, 1);
    s1 += __shfl_xor_sync(0xffffffffu, s1, 2);
    float rn0 = rsqrtf(s0 + 1e-12f);
    float rn1 = rsqrtf(s1 + 1e-12f);

    __syncthreads();

#pragma unroll
    for (int nt = 0; nt < 16; nt++) {
        int c0 = nt * 8 + 2 * (lane & 3);
        float v0 = d[nt][0] * rn0, v1 = d[nt][1] * rn0;
        float v2 = d[nt][2] * rn1, v3 = d[nt][3] * rn1;
        float g0 = __bfloat162float(__float2bfloat16(v0));
        float g1 = __bfloat162float(__float2bfloat16(v1));
        float g2 = __bfloat162float(__float2bfloat16(v2));
        float g3 = __bfloat162float(__float2bfloat16(v3));
        STS32(sb + OFF_AH + swz<128>(r0, c0), bf2(g0, g1));
        STS32(sb + OFF_AL + swz<128>(r0, c0), bf2(v0 - g0, v1 - g1));
        STS32(sb + OFF_AH + swz<128>(r1, c0), bf2(g2, g3));
        STS32(sb + OFF_AL + swz<128>(r1, c0), bf2(v2 - g2, v3 - g3));
    }
    stage_w2(g_wrth + l * 16384, sb + OFF_WB, tid);
    __syncthreads();

    zero_d(d);
    mma_gemm<128>(sb + OFF_AH, sb + OFF_WB, warp, lane, d);
    mma_gemm<128>(sb + OFF_AL, sb + OFF_WB, warp, lane, d);
    __syncthreads();
    stage_w2(g_wrtl + l * 16384, sb + OFF_WB, tid);
    __syncthreads();
    mma_gemm<128>(sb + OFF_AH, sb + OFF_WB, warp, lane, d);

    // h += s @ W_l + dec_b ; also refresh bf16 mirror
#pragma unroll
    for (int nt = 0; nt < 16; nt++) {
        int c0 = nt * 8 + 2 * (lane & 3);
        float ba = smf[128 + c0], bb = smf[128 + c0 + 1];
        if (n0 + r0 < NN) {
            float2* hp = (float2*)(h + (n0 + r0) * 128 + c0);
            float2 o = *hp;
            o.x += d[nt][0] + ba;
            o.y += d[nt][1] + bb;
            *hp = o;
            *(u32*)(g_hb + (n0 + r0) * 128 + c0) = bf2(o.x, o.y);
        }
        if (n0 + r1 < NN) {
            float2* hp = (float2*)(h + (n0 + r1) * 128 + c0);
            float2 o = *hp;
            o.x += d[nt][2] + ba;
            o.y += d[nt][3] + bb;
            *hp = o;
            *(u32*)(g_hb + (n0 + r1) * 128 + c0) = bf2(o.x, o.y);
        }
    }
}

// ---------------- host launch ----------------
extern "C" void kernel_launch(void* const* d_in, const int* in_sizes, int n_in,
                              void* d_out, int out_size) {
    const float* h0     = (const float*)d_in[0];
    const float* x0     = (const float*)d_in[1];
    const int*   ei     = (const int*)d_in[2];
    const float* eattr  = (const float*)d_in[3];
    const float* e_w1   = (const float*)d_in[4];
    const float* e_b1   = (const float*)d_in[5];
    const float* e_w2   = (const float*)d_in[6];
    const float* e_b2   = (const float*)d_in[7];
    const float* enc_w  = (const float*)d_in[8];
    const float* enc_b  = (const float*)d_in[9];
    const float* coeffs = (const float*)d_in[10];
    const float* A_re   = (const float*)d_in[11];
    const float* A_im   = (const float*)d_in[12];
    const float* dec_w  = (const float*)d_in[13];
    const float* dec_b  = (const float*)d_in[14];
    const float* c_w1   = (const float*)d_in[15];
    const float* c_b1   = (const float*)d_in[16];
    const float* c_w2   = (const float*)d_in[17];
    const float* c_b2   = (const float*)d_in[18];
    const float* c_w3   = (const float*)d_in[19];

    float* hout = (float*)d_out;
    float* xout = hout + NN * HH;

    cudaFuncSetAttribute(k_edge_msg, cudaFuncAttributeMaxDynamicSharedMemorySize, SMEM_TC);
    cudaFuncSetAttribute(k_edge_final, cudaFuncAttributeMaxDynamicSharedMemorySize, SMEM_TC);
    cudaFuncSetAttribute(k_node, cudaFuncAttributeMaxDynamicSharedMemorySize, SMEM_ND);

    void* paug; cudaGetSymbolAddress(&paug, g_aug);
    void* pxb;  cudaGetSymbolAddress(&pxb, g_xb);
    float2* XAp = (float2*)paug + 128;
    float2* XBp = (float2*)pxb;

    // 0: init
    k_init<<<(C_TOT + 255) / 256, 256>>>(h0, x0, hout, ei, A_re, A_im, coeffs,
                                         e_w1, e_w2, c_w1, c_w2, enc_w);
    // 1: zero agg
    k_zero_agg<<<(NN * HH + 255) / 256, 256>>>();
    // 2: Newton iter1 T
    k_nt<<<256, 256>>>(XAp, 32768, 256);
    // 3: edge layer 0 — PROFILED SLOT (cp.async gather)
    k_edge_msg<<<TCGRID, 512, SMEM_TC>>>(ei, eattr, e_w1, e_b1, e_b2, 0);
    // 4-8: Newton iters (3 total), ends in XB
    k_nx<<<256, 256>>>(XAp, 32768, 256, XBp, 16384, 128);
    k_nt<<<256, 256>>>(XBp, 16384, 128);
    k_nx<<<256, 256>>>(XBp, 16384, 128, XAp, 32768, 256);
    k_nt<<<256, 256>>>(XAp, 32768, 256);
    k_nx<<<256, 256>>>(XAp, 32768, 256, XBp, 16384, 128);
    // 9-12: rest of quantum precompute
    k_q<<<256, 256>>>(A_re, A_im, XBp, 16384, 128);
    k_b<<<256, 256>>>();
    k_m<<<128, 256>>>();
    k_w<<<128, 256>>>(dec_w);
    // 13: node layer 0
    k_node<<<(NN + 127) / 128, 256, SMEM_ND>>>(hout, enc_b, 0, dec_b);
    // 14: zero agg
    k_zero_agg<<<(NN * HH + 255) / 256, 256>>>();
    // 15: edge layer 1
    k_edge_msg<<<TCGRID, 512, SMEM_TC>>>(ei, eattr, e_w1 + 258 * HH,
                                         e_b1 + HH, e_b2 + HH, 1);
    // 16: node layer 1
    k_node<<<(NN + 127) / 128, 256, SMEM_ND>>>(hout, enc_b + HH, 1, dec_b + HH);
    // 17: final coordinate update
    k_edge_final<<<TCGRID, 512, SMEM_TC>>>(ei, eattr, c_w1, c_b1, c_b2,
                                           c_w3, xout);
}

// round 17
// speedup vs baseline: 1.4405x; 1.4405x over previous
#include <cuda_runtime.h>
#include <cuda_bf16.h>
#include <math.h>

#define NN 30000
#define EE 480000
#define HH 128
#define NLL 2
#define QLL 2
#define INV_NORM 0.01f

typedef unsigned long long u64;
typedef unsigned int u32;

// ---------------- device scratch (static, no allocation) ----------------
__device__ float  g_radial[EE];
__device__ float  g_cdiff[EE * 3];
__device__ float  g_agg[NN * HH];
__device__ __align__(16) __nv_bfloat16 g_hb[NN * HH];   // bf16 mirror of h
__device__ float2 g_aug[NLL * QLL * 128 * 256];
__device__ float2 g_xb[NLL * QLL * 128 * 128];
__device__ float2 g_gk[NLL * QLL * 128 * 128];
__device__ float2 g_qm[NLL * QLL * 128 * 128];
__device__ float2 g_bp[NLL * QLL * 128 * 128];
__device__ float2 g_ml[NLL * 128 * 128];
__device__ int    g_perm[128];
__device__ __align__(16) __nv_bfloat16 g_w1t[NLL * 128 * 256];
__device__ __align__(16) __nv_bfloat16 g_w2t[NLL * 128 * 128];
__device__ __align__(16) __nv_bfloat16 g_cw1t[128 * 256];
__device__ __align__(16) __nv_bfloat16 g_cw2t[128 * 128];
__device__ __align__(16) __nv_bfloat16 g_encth[NLL * 128 * 256];
__device__ __align__(16) __nv_bfloat16 g_enctl[NLL * 128 * 256];
__device__ __align__(16) __nv_bfloat16 g_wrth[NLL * 128 * 128];
__device__ __align__(16) __nv_bfloat16 g_wrtl[NLL * 128 * 128];

__device__ __forceinline__ float2 cmulf(float2 a, float2 b) {
    return make_float2(a.x * b.x - a.y * b.y, a.x * b.y + a.y * b.x);
}
__device__ __forceinline__ float siluf(float v) {
    float t;
    asm("tanh.approx.f32 %0, %1;" : "=f"(t) : "f"(0.5f * v));
    return 0.5f * v * (1.f + t);
}

__device__ __forceinline__ void red_add_v4(float* p, float a, float b, float c, float d) {
    asm volatile("red.global.add.v4.f32 [%0], {%1, %2, %3, %4};"
                 :: "l"(p), "f"(a), "f"(b), "f"(c), "f"(d) : "memory");
}
__device__ __forceinline__ u32 bf2(float lo, float hi) {
    u32 r; asm("cvt.rn.bf16x2.f32 %0, %1, %2;" : "=r"(r) : "f"(hi), "f"(lo)); return r;
}
__device__ __forceinline__ u32 smem_u32(const void* p) {
    u32 a; asm("{ .reg .u64 t; cvta.to.shared.u64 t, %1; cvt.u32.u64 %0, t; }"
               : "=r"(a) : "l"(p));
    return a;
}
#define STS128(addr, a, b, c, d) \
    asm volatile("st.shared.v4.b32 [%0], {%1, %2, %3, %4};" \
                 :: "r"(addr), "r"(a), "r"(b), "r"(c), "r"(d) : "memory")
#define STS32(addr, a) \
    asm volatile("st.shared.b32 [%0], %1;" :: "r"(addr), "r"(a) : "memory")

// ---------------- portable tensor-core primitives ----------
__device__ __forceinline__ void ldsm4(u32& r0, u32& r1, u32& r2, u32& r3, u32 addr) {
    asm volatile("ldmatrix.sync.aligned.m8n8.x4.shared.b16 {%0,%1,%2,%3}, [%4];"
                 : "=r"(r0), "=r"(r1), "=r"(r2), "=r"(r3) : "r"(addr));
}
__device__ __forceinline__ void mma16816(float* d, u32 a0, u32 a1, u32 a2, u32 a3,
                                         u32 b0, u32 b1) {
    asm volatile(
        "mma.sync.aligned.m16n8k16.row.col.f32.bf16.bf16.f32 "
        "{%0,%1,%2,%3}, {%4,%5,%6,%7}, {%8,%9}, {%0,%1,%2,%3};"
        : "+f"(d[0]), "+f"(d[1]), "+f"(d[2]), "+f"(d[3])
        : "r"(a0), "r"(a1), "r"(a2), "r"(a3), "r"(b0), "r"(b1));
}

template <int K>
__device__ __forceinline__ u32 swz(int r, int k) {
    return (u32)(r * (K * 2) + ((((k >> 3) ^ (r & 7)) << 4) | ((k & 7) << 1)));
}

// ---- 256-thread full-width GEMM (node kernel) ----
template <int K>
__device__ __forceinline__ void mma_gemm(u32 sbA, u32 sbB, int warp, int lane,
                                         float d[16][4]) {
    int arow = warp * 16 + (lane & 15);
    int akoff = (lane >> 4) << 3;
    int brow = (lane & 7) + ((lane & 16) >> 1);
    int bkoff = (lane & 8);
#pragma unroll
    for (int ks = 0; ks < K / 16; ks++) {
        int k0 = ks * 16;
        u32 a0, a1, a2, a3;
        ldsm4(a0, a1, a2, a3, sbA + swz<K>(arow, k0 + akoff));
#pragma unroll
        for (int u = 0; u < 8; u++) {
            u32 b0, b1, b2, b3;
            ldsm4(b0, b1, b2, b3, sbB + swz<K>(16 * u + brow, k0 + bkoff));
            mma16816(d[2 * u], a0, a1, a2, a3, b0, b1);
            mma16816(d[2 * u + 1], a0, a1, a2, a3, b2, b3);
        }
    }
}
__device__ __forceinline__ void zero_d(float d[16][4]) {
#pragma unroll
    for (int i = 0; i < 16; i++)
#pragma unroll
        for (int j = 0; j < 4; j++) d[i][j] = 0.f;
}

// ---- 512-thread quad-tile GEMM (edge kernels): warp (rg, nh) covers
// rows [32rg, 32rg+32) x cols [32nh, 32nh+32)
template <int K>
__device__ __forceinline__ void mma_gemm_q(u32 sbA, u32 sbB, int rg, int nh,
                                           int lane, float d[8][4]) {
    int arow = rg * 32 + (lane & 15);
    int akoff = (lane >> 4) << 3;
    int brow = nh * 32 + (lane & 7) + ((lane & 16) >> 1);
    int bkoff = (lane & 8);
#pragma unroll
    for (int ks = 0; ks < K / 16; ks++) {
        int k0 = ks * 16;
        u32 a[2][4], b[2][4];
        ldsm4(a[0][0], a[0][1], a[0][2], a[0][3], sbA + swz<K>(arow, k0 + akoff));
        ldsm4(a[1][0], a[1][1], a[1][2], a[1][3], sbA + swz<K>(arow + 16, k0 + akoff));
        ldsm4(b[0][0], b[0][1], b[0][2], b[0][3], sbB + swz<K>(brow, k0 + bkoff));
        ldsm4(b[1][0], b[1][1], b[1][2], b[1][3], sbB + swz<K>(brow + 16, k0 + bkoff));
#pragma unroll
        for (int ai = 0; ai < 2; ai++)
#pragma unroll
            for (int bj = 0; bj < 2; bj++) {
                mma16816(d[ai * 4 + bj * 2 + 0], a[ai][0], a[ai][1], a[ai][2], a[ai][3],
                         b[bj][0], b[bj][1]);
                mma16816(d[ai * 4 + bj * 2 + 1], a[ai][0], a[ai][1], a[ai][2], a[ai][3],
                         b[bj][2], b[bj][3]);
            }
    }
}
__device__ __forceinline__ void zero_d8(float d[8][4]) {
#pragma unroll
    for (int i = 0; i < 8; i++)
#pragma unroll
        for (int j = 0; j < 4; j++) d[i][j] = 0.f;
}

// ---------------- merged init ----------------
#define C_COPY (NN * HH)
#define C_GEO  EE
#define C_AUG  (NLL * QLL * 128 * 256)
#define C_GK   (NLL * QLL * 128 * 128)
#define C_W1T  (NLL * 128 * 256)
#define C_W2T  (NLL * 128 * 128)
#define C_CW1  (128 * 256)
#define C_CW2  (128 * 128)
#define C_ENC  (NLL * 128 * 256)
#define C_TOT  (C_COPY + C_GEO + C_AUG + C_GK + C_W1T + C_W2T + C_CW1 + C_CW2 + C_ENC + 1)

__global__ void k_init(const float* __restrict__ h0, const float* __restrict__ x0,
                       float* __restrict__ out, const int* __restrict__ ei,
                       const float* __restrict__ Are, const float* __restrict__ Aim,
                       const float* __restrict__ coeffs, const float* __restrict__ e_w1,
                       const float* __restrict__ e_w2, const float* __restrict__ c_w1,
                       const float* __restrict__ c_w2, const float* __restrict__ enc_w) {
    int idx = blockIdx.x * 256 + threadIdx.x;
    if (idx < C_COPY) {
        float v = h0[idx];
        out[idx] = v;
        g_hb[idx] = __float2bfloat16(v);
        if (idx < NN * 3) out[C_COPY + idx] = x0[idx];
        return;
    }
    idx -= C_COPY;
    if (idx < C_GEO) {
        int e = idx;
        int r = ei[e], c = ei[EE + e];
        float dx = x0[r * 3 + 0] - x0[c * 3 + 0];
        float dy = x0[r * 3 + 1] - x0[c * 3 + 1];
        float dz = x0[r * 3 + 2] - x0[c * 3 + 2];
        float rad = dx * dx + dy * dy + dz * dz;
        g_radial[e] = rad;
        float s = 1.f / (sqrtf(rad + 1e-8f) + 1.0f);
        g_cdiff[e * 3 + 0] = dx * s;
        g_cdiff[e * 3 + 1] = dy * s;
        g_cdiff[e * 3 + 2] = dz * s;
        return;
    }
    idx -= C_GEO;
    if (idx < C_AUG) {
        int mat = idx >> 15;
        int rem = idx & 32767;
        int i = rem >> 8, c = rem & 255;
        const float* Ar = Are + mat * 16384;
        const float* Ai = Aim + mat * 16384;
        float2 v;
        if (c < 128) {
            v.x = Ar[i * 128 + c] + Ar[c * 128 + i];
            v.y = Ai[i * 128 + c] - Ai[c * 128 + i] + (i == c ? 1.f : 0.f);
        } else {
            int cc = c - 128;
            v.x = Ar[i * 128 + cc] + Ar[cc * 128 + i];
            v.y = Ai[i * 128 + cc] - Ai[cc * 128 + i] - (i == cc ? 1.f : 0.f);
        }
        g_aug[idx] = v;
        return;
    }
    idx -= C_AUG;
    if (idx < C_GK) {
        int mat = idx >> 14;
        int rem = idx & 16383;
        int r = rem >> 7, c = rem & 127;
        float a = coeffs[mat * 2 + 0], b = coeffs[mat * 2 + 1];
        float ca = cosf(0.5f * a), sa = sinf(0.5f * a);
        float cb = cosf(0.5f * b), sb = sinf(0.5f * b);
        float2 G[2][2];
        G[0][0] = make_float2(cb * ca, sb * sa);
        G[0][1] = make_float2(-sb * ca, -cb * sa);
        G[1][0] = make_float2(sb * ca, -cb * sa);
        G[1][1] = make_float2(cb * ca, -sb * sa);
        float2 p = G[(r >> 6) & 1][(c >> 6) & 1];
#pragma unroll
        for (int t = 5; t >= 0; t--) p = cmulf(p, G[(r >> t) & 1][(c >> t) & 1]);
        g_gk[idx] = p;
        return;
    }
    idx -= C_GK;
    if (idx < C_W1T) {
        int l = idx / (128 * 256);
        int rem = idx - l * 128 * 256;
        int n = rem >> 8, k = rem & 255;
        g_w1t[idx] = __float2bfloat16(e_w1[(l * 258 + k) * 128 + n]);
        return;
    }
    idx -= C_W1T;
    if (idx < C_W2T) {
        int l = idx >> 14;
        int rem = idx & 16383;
        int n = rem >> 7, k = rem & 127;
        g_w2t[idx] = __float2bfloat16(e_w2[(l * 128 + k) * 128 + n]);
        return;
    }
    idx -= C_W2T;
    if (idx < C_CW1) {
        int n = idx >> 8, k = idx & 255;
        g_cw1t[idx] = __float2bfloat16(c_w1[k * 128 + n]);
        return;
    }
    idx -= C_CW1;
    if (idx < C_CW2) {
        int n = idx >> 7, k = idx & 127;
        g_cw2t[idx] = __float2bfloat16(c_w2[k * 128 + n]);
        return;
    }
    idx -= C_CW2;
    if (idx < C_ENC) {
        int l = idx >> 15;
        int rem = idx & 32767;
        int n = rem >> 8, k = rem & 255;
        float x = enc_w[(l * 256 + k) * 128 + n];
        __nv_bfloat16 hb = __float2bfloat16(x);
        float lo = x - __bfloat162float(hb);
        g_encth[l * 32768 + n * 256 + k] = hb;
        g_enctl[l * 32768 + n * 256 + k] = __float2bfloat16(lo);
        return;
    }
    idx -= C_ENC;
    if (idx == 0) {
        int g[128], tmp[128];
        bool first = true;
        for (int p = 0; p < 7; p++) {
            int c = (p < 6) ? p : 6;
            int t = (p < 6) ? p + 1 : 0;
            for (int i = 0; i < 128; i++) {
                int cb = (i >> (6 - c)) & 1;
                int f = i ^ (cb << (6 - t));
                tmp[i] = first ? f : g[f];
            }
            for (int i = 0; i < 128; i++) g[i] = tmp[i];
            first = false;
        }
        for (int i = 0; i < 128; i++) g_perm[i] = g[i];
    }
}

// ---------------- Newton inverse (chip-wide grids) ----------------
__global__ void k_nt(const float2* __restrict__ X, int mstride, int rstride) {
    int g = blockIdx.x * 256 + threadIdx.x;
    int mat = g >> 14;
    int e = g & 16383;
    int i = e >> 7, j = e & 127;
    const float2* M = g_aug + mat * 32768;
    const float2* Xm = X + mat * mstride;
    float2 acc = make_float2(0.f, 0.f);
#pragma unroll 4
    for (int k = 0; k < 128; k++) {
        float2 m = M[i * 256 + k];
        float2 x = Xm[k * rstride + j];
        acc.x += m.x * x.x - m.y * x.y;
        acc.y += m.x * x.y + m.y * x.x;
    }
    g_bp[g] = acc;
}

__global__ void k_nx(const float2* __restrict__ X, int mstride, int rstride,
                     float2* __restrict__ Xo, int omstride, int orstride) {
    int g = blockIdx.x * 256 + threadIdx.x;
    int mat = g >> 14;
    int e = g & 16383;
    int i = e >> 7, j = e & 127;
    const float2* Xm = X + mat * mstride;
    const float2* Tm = g_bp + mat * 16384;
    float2 xij = Xm[i * rstride + j];
    float2 acc = make_float2(2.f * xij.x, 2.f * xij.y);
#pragma unroll 4
    for (int k = 0; k < 128; k++) {
        float2 x = Xm[i * rstride + k];
        float2 t = Tm[k * 128 + j];
        acc.x -= x.x * t.x - x.y * t.y;
        acc.y -= x.x * t.y + x.y * t.x;
    }
    Xo[mat * omstride + i * orstride + j] = acc;
}

__global__ void k_q(const float* __restrict__ Are, const float* __restrict__ Aim,
                    const float2* __restrict__ X, int mstride, int rstride) {
    int g = blockIdx.x * 256 + threadIdx.x;
    int mat = g >> 14;
    int e = g & 16383;
    int i = e >> 7, j = e & 127;
    const float* Ar = Are + mat * 16384;
    const float* Ai = Aim + mat * 16384;
    const float2* Xm = X + mat * mstride;
    float2 acc = make_float2(0.f, 0.f);
#pragma unroll 4
    for (int k = 0; k < 128; k++) {
        float2 mm = make_float2(Ar[i * 128 + k] + Ar[k * 128 + i],
                                Ai[i * 128 + k] - Ai[k * 128 + i] - (i == k ? 1.f : 0.f));
        float2 pv = Xm[k * rstride + j];
        acc.x += mm.x * pv.x - mm.y * pv.y;
        acc.y += mm.x * pv.y + mm.y * pv.x;
    }
    g_qm[g] = acc;
}

__global__ void k_b() {
    int g = blockIdx.x * 256 + threadIdx.x;
    int mat = g >> 14;
    int e = g & 16383;
    int i = e >> 7, k = e & 127;
    const float2* Q = g_qm + mat * 16384;
    const float2* Gk = g_gk + mat * 16384 + g_perm[k] * 128;
    float2 acc = make_float2(0.f, 0.f);
#pragma unroll 4
    for (int m = 0; m < 128; m++) {
        float2 q = Q[m * 128 + i];
        float2 gk = Gk[m];
        acc.x += q.x * gk.x - q.y * gk.y;
        acc.y += q.x * gk.y + q.y * gk.x;
    }
    g_bp[g] = acc;
}

__global__ void k_m() {
    int g = blockIdx.x * 256 + threadIdx.x;
    int l = g >> 14;
    int e = g & 16383;
    int i = e >> 7, j = e & 127;
    const float2* B0 = g_bp + (2 * l) * 16384;
    const float2* B1 = g_bp + (2 * l + 1) * 16384;
    float2 acc = make_float2(0.f, 0.f);
#pragma unroll 4
    for (int k = 0; k < 128; k++) {
        float2 a = B0[i * 128 + k];
        float2 b = B1[k * 128 + j];
        acc.x += a.x * b.x - a.y * b.y;
        acc.y += a.x * b.y + a.y * b.x;
    }
    g_ml[g] = acc;
}

__global__ void k_w(const float* __restrict__ decW) {
    int g = blockIdx.x * 256 + threadIdx.x;
    int l = g >> 14;
    int e = g & 16383;
    int k = e >> 7, n = e & 127;
    const float2* M = g_ml + l * 16384 + k * 128;
    const float* W = decW + l * 16384;
    float acc = 0.f;
#pragma unroll 4
    for (int m = 0; m < 128; m++) acc += M[m].x * W[m * 128 + n];
    __nv_bfloat16 hb = __float2bfloat16(acc);
    float lo = acc - __bfloat162float(hb);
    g_wrth[l * 16384 + n * 128 + k] = hb;
    g_wrtl[l * 16384 + n * 128 + k] = __float2bfloat16(lo);
}

__global__ void k_zero_agg() {
    int i = blockIdx.x * blockDim.x + threadIdx.x;
    if (i < NN * HH) g_agg[i] = 0.f;
}

// ================= staging helpers =================
__device__ __forceinline__ void stage_w1(const __nv_bfloat16* __restrict__ src,
                                         u32 dst, int tid) {
    int lane = tid & 31, wy = tid >> 5;
    for (int it = 0; it < 16; it++) {
        int n = wy + 8 * it;
        int k0 = lane * 8;
        uint4 v = *(const uint4*)(src + n * 256 + k0);
        STS128(dst + swz<256>(n, k0), v.x, v.y, v.z, v.w);
    }
}
__device__ __forceinline__ void stage_w2(const __nv_bfloat16* __restrict__ src,
                                         u32 dst, int tid) {
    int lane = tid & 31, wy = tid >> 5;
    if (lane < 16) {
        for (int it = 0; it < 16; it++) {
            int n = wy + 8 * it;
            int k0 = lane * 8;
            uint4 v = *(const uint4*)(src + n * 128 + k0);
            STS128(dst + swz<128>(n, k0), v.x, v.y, v.z, v.w);
        }
    }
}
__device__ __forceinline__ void stage_w1_512(const __nv_bfloat16* __restrict__ src,
                                             u32 dst, int tid) {
    int lane = tid & 31, wy = tid >> 5;
    for (int it = 0; it < 8; it++) {
        int n = wy + 16 * it;
        int k0 = lane * 8;
        uint4 v = *(const uint4*)(src + n * 256 + k0);
        STS128(dst + swz<256>(n, k0), v.x, v.y, v.z, v.w);
    }
}
__device__ __forceinline__ void stage_w2_512(const __nv_bfloat16* __restrict__ src,
                                             u32 dst, int tid) {
    int lane = tid & 31, wy = tid >> 5;
    if (lane < 16) {
        for (int it = 0; it < 8; it++) {
            int n = wy + 16 * it;
            int k0 = lane * 8;
            uint4 v = *(const uint4*)(src + n * 128 + k0);
            STS128(dst + swz<128>(n, k0), v.x, v.y, v.z, v.w);
        }
    }
}

// ================= mma.sync edge kernels (512 threads, 32x32 tiles) ============
#define OFF_RIDX 0
#define OFF_RS   512
#define OFF_ES   1024
#define OFF_B1S  1536
#define OFF_B2S  2048
#define OFF_WR0  2560
#define OFF_WR1  3072
#define OFF_W3S  3584
#define OFF_TSUM 4096
#define OFF_A1   8192
#define OFF_W1S  (OFF_A1 + 65536)
#define OFF_A2   (OFF_W1S + 65536)
#define OFF_W2S  (OFF_A2 + 32768)
#define SMEM_TC  (OFF_W2S + 32768)
#define NTILES   (EE / 128)
#define TCGRID   148

// gather from bf16 mirror: 1 LDG.128 + 1 STS.128 per thread-iter
__device__ __forceinline__ void gather_tile(const int* __restrict__ ei,
                                            const float* __restrict__ eattr,
                                            u32 sb, float* smf, int* smi,
                                            int e0, int tid) {
    int lane = tid & 31, wy = tid >> 5;
    for (int it = 0; it < 8; it++) {
        int m = wy + 16 * it;
        int e = e0 + m;
        int r = ei[e], c = ei[EE + e];
        if (lane == 0) {
            smi[OFF_RIDX / 4 + m] = r;
            smf[OFF_RS / 4 + m] = g_radial[e];
            smf[OFF_ES / 4 + m] = eattr[e];
        }
        int src = (lane < 16) ? r : c;
        int koff = (lane & 15) * 8;
        uint4 v = *(const uint4*)(g_hb + src * 128 + koff);
        STS128(sb + OFF_A1 + swz<256>(m, lane * 8), v.x, v.y, v.z, v.w);
    }
}

__device__ __forceinline__ void epi1_q(float d[8][4], const float* smf, u32 sb,
                                       int rg, int nh, int lane) {
#pragma unroll
    for (int ai = 0; ai < 2; ai++) {
        int r0 = rg * 32 + ai * 16 + (lane >> 2);
        int r1 = r0 + 8;
        float rad0 = smf[OFF_RS / 4 + r0], ea0 = smf[OFF_ES / 4 + r0];
        float rad1 = smf[OFF_RS / 4 + r1], ea1 = smf[OFF_ES / 4 + r1];
#pragma unroll
        for (int bj = 0; bj < 2; bj++)
#pragma unroll
            for (int nt2 = 0; nt2 < 2; nt2++) {
                int idx = ai * 4 + bj * 2 + nt2;
                int c0 = nh * 32 + bj * 16 + nt2 * 8 + 2 * (lane & 3);
                float b1a = smf[OFF_B1S / 4 + c0], b1b = smf[OFF_B1S / 4 + c0 + 1];
                float w0a = smf[OFF_WR0 / 4 + c0], w0b = smf[OFF_WR0 / 4 + c0 + 1];
                float w1a = smf[OFF_WR1 / 4 + c0], w1b = smf[OFF_WR1 / 4 + c0 + 1];
                float v0 = siluf(d[idx][0] + b1a + rad0 * w0a + ea0 * w1a);
                float v1 = siluf(d[idx][1] + b1b + rad0 * w0b + ea0 * w1b);
                float v2 = siluf(d[idx][2] + b1a + rad1 * w0a + ea1 * w1a);
                float v3 = siluf(d[idx][3] + b1b + rad1 * w0b + ea1 * w1b);
                STS32(sb + OFF_A2 + swz<128>(r0, c0), bf2(v0, v1));
                STS32(sb + OFF_A2 + swz<128>(r1, c0), bf2(v2, v3));
            }
    }
}

__global__ void __launch_bounds__(512, 1) k_edge_msg(
    const int* __restrict__ ei, const float* __restrict__ eattr,
    const float* __restrict__ w1f, const float* __restrict__ b1,
    const float* __restrict__ b2, int l) {
    extern __shared__ char sm[];
    u32 sb = smem_u32(sm);
    float* smf = (float*)sm;
    int* smi = (int*)sm;
    int tid = threadIdx.x;
    int warp = tid >> 5, lane = tid & 31;
    int rg = warp & 3, nh = warp >> 2;

    stage_w1_512(g_w1t + l * 128 * 256, sb + OFF_W1S, tid);
    stage_w2_512(g_w2t + l * 128 * 128, sb + OFF_W2S, tid);
    if (tid < 128) {
        smf[OFF_B1S / 4 + tid] = b1[tid];
        smf[OFF_B2S / 4 + tid] = b2[tid];
        smf[OFF_WR0 / 4 + tid] = w1f[256 * 128 + tid];
        smf[OFF_WR1 / 4 + tid] = w1f[257 * 128 + tid];
    }
    __syncthreads();

    float d[8][4];
    for (int t = blockIdx.x; t < NTILES; t += TCGRID) {
        gather_tile(ei, eattr, sb, smf, smi, t * 128, tid);
        __syncthreads();
        zero_d8(d);
        mma_gemm_q<256>(sb + OFF_A1, sb + OFF_W1S, rg, nh, lane, d);
        epi1_q(d, smf, sb, rg, nh, lane);
        __syncthreads();
        zero_d8(d);
        mma_gemm_q<128>(sb + OFF_A2, sb + OFF_W2S, rg, nh, lane, d);
#pragma unroll
        for (int ai = 0; ai < 2; ai++) {
            int r0 = rg * 32 + ai * 16 + (lane >> 2);
            int r1 = r0 + 8;
            int row0 = smi[OFF_RIDX / 4 + r0];
            int row1 = smi[OFF_RIDX / 4 + r1];
#pragma unroll
            for (int bj = 0; bj < 2; bj++)
#pragma unroll
                for (int nt2 = 0; nt2 < 2; nt2++) {
                    int idx = ai * 4 + bj * 2 + nt2;
                    int c0 = nh * 32 + bj * 16 + nt2 * 8 + 2 * (lane & 3);
                    int cbase = nh * 32 + bj * 16 + nt2 * 8 + ((lane & 2) << 1);
                    float b2a = smf[OFF_B2S / 4 + c0], b2b = smf[OFF_B2S / 4 + c0 + 1];
                    float a0 = siluf(d[idx][0] + b2a) * INV_NORM;
                    float a1 = siluf(d[idx][1] + b2b) * INV_NORM;
                    float a2 = siluf(d[idx][2] + b2a) * INV_NORM;
                    float a3 = siluf(d[idx][3] + b2b) * INV_NORM;
                    float p0 = __shfl_xor_sync(0xffffffffu, a0, 1);
                    float p1 = __shfl_xor_sync(0xffffffffu, a1, 1);
                    float p2 = __shfl_xor_sync(0xffffffffu, a2, 1);
                    float p3 = __shfl_xor_sync(0xffffffffu, a3, 1);
                    if (!(lane & 1)) {
                        red_add_v4(g_agg + row0 * HH + cbase, a0, a1, p0, p1);
                        red_add_v4(g_agg + row1 * HH + cbase, a2, a3, p2, p3);
                    }
                }
        }
        __syncthreads();
    }
}

__global__ void __launch_bounds__(512, 1) k_edge_final(
    const int* __restrict__ ei, const float* __restrict__ eattr,
    const float* __restrict__ cw1f, const float* __restrict__ cb1,
    const float* __restrict__ cb2, const float* __restrict__ cw3,
    float* __restrict__ xout) {
    extern __shared__ char sm[];
    u32 sb = smem_u32(sm);
    float* smf = (float*)sm;
    int* smi = (int*)sm;
    int tid = threadIdx.x;
    int warp = tid >> 5, lane = tid & 31;
    int rg = warp & 3, nh = warp >> 2;

    stage_w1_512(g_cw1t, sb + OFF_W1S, tid);
    stage_w2_512(g_cw2t, sb + OFF_W2S, tid);
    if (tid < 128) {
        smf[OFF_B1S / 4 + tid] = cb1[tid];
        smf[OFF_B2S / 4 + tid] = cb2[tid];
        smf[OFF_WR0 / 4 + tid] = cw1f[256 * 128 + tid];
        smf[OFF_WR1 / 4 + tid] = cw1f[257 * 128 + tid];
        smf[OFF_W3S / 4 + tid] = cw3[tid];
    }
    __syncthreads();

    float d[8][4];
    for (int t = blockIdx.x; t < NTILES; t += TCGRID) {
        int e0 = t * 128;
        gather_tile(ei, eattr, sb, smf, smi, e0, tid);
        __syncthreads();
        zero_d8(d);
        mma_gemm_q<256>(sb + OFF_A1, sb + OFF_W1S, rg, nh, lane, d);
        epi1_q(d, smf, sb, rg, nh, lane);
        __syncthreads();
        zero_d8(d);
        mma_gemm_q<128>(sb + OFF_A2, sb + OFF_W2S, rg, nh, lane, d);
#pragma unroll
        for (int ai = 0; ai < 2; ai++) {
            int r0 = rg * 32 + ai * 16 + (lane >> 2);
            int r1 = r0 + 8;
            float t0 = 0.f, t1 = 0.f;
#pragma unroll
            for (int bj = 0; bj < 2; bj++)
#pragma unroll
                for (int nt2 = 0; nt2 < 2; nt2++) {
                    int idx = ai * 4 + bj * 2 + nt2;
                    int c0 = nh * 32 + bj * 16 + nt2 * 8 + 2 * (lane & 3);
                    float b2a = smf[OFF_B2S / 4 + c0], b2b = smf[OFF_B2S / 4 + c0 + 1];
                    float w3a = smf[OFF_W3S / 4 + c0], w3b = smf[OFF_W3S / 4 + c0 + 1];
                    t0 += siluf(d[idx][0] + b2a) * w3a + siluf(d[idx][1] + b2b) * w3b;
                    t1 += siluf(d[idx][2] + b2a) * w3a + siluf(d[idx][3] + b2b) * w3b;
                }
            t0 += __shfl_xor_sync(0xffffffffu, t0, 1);
            t0 += __shfl_xor_sync(0xffffffffu, t0, 2);
            t1 += __shfl_xor_sync(0xffffffffu, t1, 1);
            t1 += __shfl_xor_sync(0xffffffffu, t1, 2);
            if (!(lane & 3)) {
                smf[OFF_TSUM / 4 + nh * 128 + r0] = t0;
                smf[OFF_TSUM / 4 + nh * 128 + r1] = t1;
            }
        }
        __syncthreads();
        if (tid < 128) {
            int e = e0 + tid;
            int r = smi[OFF_RIDX / 4 + tid];
            float tt = (smf[OFF_TSUM / 4 + tid] + smf[OFF_TSUM / 4 + 128 + tid] +
                        smf[OFF_TSUM / 4 + 256 + tid] + smf[OFF_TSUM / 4 + 384 + tid]) *
                       INV_NORM;
            atomicAdd(&xout[r * 3 + 0], g_cdiff[e * 3 + 0] * tt);
            atomicAdd(&xout[r * 3 + 1], g_cdiff[e * 3 + 1] * tt);
            atomicAdd(&xout[r * 3 + 2], g_cdiff[e * 3 + 2] * tt);
        }
        __syncthreads();
    }
}

// ================= node kernel (256 threads, split-bf16) =========
#define OFF_AH 4096
#define OFF_AL (OFF_AH + 65536)
#define OFF_WB (OFF_AL + 65536)
#define SMEM_ND (OFF_WB + 65536)

__device__ __forceinline__ void gather_node(const float* __restrict__ h, int n0,
                                            u32 sb, int tid) {
    int lane = tid & 31, wy = tid >> 5;
    for (int it = 0; it < 16; it++) {
        int m = wy + 8 * it;
        int n = n0 + m;
        float4 v0 = make_float4(0.f, 0.f, 0.f, 0.f), v1 = v0;
        if (n < NN) {
            const float* base = (lane < 16) ? (h + n * 128 + lane * 8)
                                            : (g_agg + n * 128 + lane * 8 - 128);
            v0 = ((const float4*)base)[0];
            v1 = ((const float4*)base)[1];
        }
        float a[8] = {v0.x, v0.y, v0.z, v0.w, v1.x, v1.y, v1.z, v1.w};
        u32 hp[4], lp[4];
#pragma unroll
        for (int q = 0; q < 4; q++) {
            float f0 = a[2 * q], f1 = a[2 * q + 1];
            float g0 = __bfloat162float(__float2bfloat16(f0));
            float g1 = __bfloat162float(__float2bfloat16(f1));
            hp[q] = bf2(g0, g1);
            lp[q] = bf2(f0 - g0, f1 - g1);
        }
        u32 off = swz<256>(m, lane * 8);
        STS128(sb + OFF_AH + off, hp[0], hp[1], hp[2], hp[3]);
        STS128(sb + OFF_AL + off, lp[0], lp[1], lp[2], lp[3]);
    }
}

__global__ void __launch_bounds__(256, 1) k_node(
    float* __restrict__ h, const float* __restrict__ encB, int l,
    const float* __restrict__ decB) {
    extern __shared__ char sm[];
    u32 sb = smem_u32(sm);
    float* smf = (float*)sm;
    int tid = threadIdx.x;
    int warp = tid >> 5, lane = tid & 31;
    int n0 = blockIdx.x * 128;

    if (tid < 128) {
        smf[tid] = encB[tid];
        smf[128 + tid] = decB[tid];
    }
    gather_node(h, n0, sb, tid);
    stage_w1(g_encth + l * 32768, sb + OFF_WB, tid);
    __syncthreads();

    float d[16][4];
    zero_d(d);
    mma_gemm<256>(sb + OFF_AH, sb + OFF_WB, warp, lane, d);
    mma_gemm<256>(sb + OFF_AL, sb + OFF_WB, warp, lane, d);
    __syncthreads();
    stage_w1(g_enctl + l * 32768, sb + OFF_WB, tid);
    __syncthreads();
    mma_gemm<256>(sb + OFF_AH, sb + OFF_WB, warp, lane, d);

    int r0 = warp * 16 + (lane >> 2);
    int r1 = r0 + 8;
    float s0 = 0.f, s1 = 0.f;
#pragma unroll
    for (int nt = 0; nt < 16; nt++) {
        int c0 = nt * 8 + 2 * (lane & 3);
        float ba = smf[c0], bb = smf[c0 + 1];
        d[nt][0] += ba; d[nt][1] += bb; d[nt][2] += ba; d[nt][3] += bb;
        s0 += d[nt][0] * d[nt][0] + d[nt][1] * d[nt][1];
        s1 += d[nt][2] * d[nt][2] + d[nt][3] * d[nt][3];
    }
    s0 += __shfl_xor_sync(0xffffffffu, s0, 1);
    s0 += __shfl_xor_sync(0xffffffffu, s0, 2);
    s1 += __shfl_xor_sync(0xffffffffu, s1, 1);
    s1 += __shfl_xor_sync(0xffffffffu, s1, 2);
    float rn0 = rsqrtf(s0 + 1e-12f);
    float rn1 = rsqrtf(s1 + 1e-12f);

    __syncthreads();

#pragma unroll
    for (int nt = 0; nt < 16; nt++) {
        int c0 = nt * 8 + 2 * (lane & 3);
        float v0 = d[nt][0] * rn0, v1 = d[nt][1] * rn0;
        float v2 = d[nt][2] * rn1, v3 = d[nt][3] * rn1;
        float g0 = __bfloat162float(__float2bfloat16(v0));
        float g1 = __bfloat162float(__float2bfloat16(v1));
        float g2 = __bfloat162float(__float2bfloat16(v2));
        float g3 = __bfloat162float(__float2bfloat16(v3));
        STS32(sb + OFF_AH + swz<128>(r0, c0), bf2(g0, g1));
        STS32(sb + OFF_AL + swz<128>(r0, c0), bf2(v0 - g0, v1 - g1));
        STS32(sb + OFF_AH + swz<128>(r1, c0), bf2(g2, g3));
        STS32(sb + OFF_AL + swz<128>(r1, c0), bf2(v2 - g2, v3 - g3));
    }
    stage_w2(g_wrth + l * 16384, sb + OFF_WB, tid);
    __syncthreads();

    zero_d(d);
    mma_gemm<128>(sb + OFF_AH, sb + OFF_WB, warp, lane, d);
    mma_gemm<128>(sb + OFF_AL, sb + OFF_WB, warp, lane, d);
    __syncthreads();
    stage_w2(g_wrtl + l * 16384, sb + OFF_WB, tid);
    __syncthreads();
    mma_gemm<128>(sb + OFF_AH, sb + OFF_WB, warp, lane, d);

    // h += s @ W_l + dec_b ; refresh bf16 mirror
#pragma unroll
    for (int nt = 0; nt < 16; nt++) {
        int c0 = nt * 8 + 2 * (lane & 3);
        float ba = smf[128 + c0], bb = smf[128 + c0 + 1];
        if (n0 + r0 < NN) {
            float2* hp = (float2*)(h + (n0 + r0) * 128 + c0);
            float2 o = *hp;
            o.x += d[nt][0] + ba;
            o.y += d[nt][1] + bb;
            *hp = o;
            *(u32*)(g_hb + (n0 + r0) * 128 + c0) = bf2(o.x, o.y);
        }
        if (n0 + r1 < NN) {
            float2* hp = (float2*)(h + (n0 + r1) * 128 + c0);
            float2 o = *hp;
            o.x += d[nt][2] + ba;
            o.y += d[nt][3] + bb;
            *hp = o;
            *(u32*)(g_hb + (n0 + r1) * 128 + c0) = bf2(o.x, o.y);
        }
    }
}

// ---------------- host launch ----------------
extern "C" void kernel_launch(void* const* d_in, const int* in_sizes, int n_in,
                              void* d_out, int out_size) {
    const float* h0     = (const float*)d_in[0];
    const float* x0     = (const float*)d_in[1];
    const int*   ei     = (const int*)d_in[2];
    const float* eattr  = (const float*)d_in[3];
    const float* e_w1   = (const float*)d_in[4];
    const float* e_b1   = (const float*)d_in[5];
    const float* e_w2   = (const float*)d_in[6];
    const float* e_b2   = (const float*)d_in[7];
    const float* enc_w  = (const float*)d_in[8];
    const float* enc_b  = (const float*)d_in[9];
    const float* coeffs = (const float*)d_in[10];
    const float* A_re   = (const float*)d_in[11];
    const float* A_im   = (const float*)d_in[12];
    const float* dec_w  = (const float*)d_in[13];
    const float* dec_b  = (const float*)d_in[14];
    const float* c_w1   = (const float*)d_in[15];
    const float* c_b1   = (const float*)d_in[16];
    const float* c_w2   = (const float*)d_in[17];
    const float* c_b2   = (const float*)d_in[18];
    const float* c_w3   = (const float*)d_in[19];

    float* hout = (float*)d_out;
    float* xout = hout + NN * HH;

    cudaFuncSetAttribute(k_edge_msg, cudaFuncAttributeMaxDynamicSharedMemorySize, SMEM_TC);
    cudaFuncSetAttribute(k_edge_final, cudaFuncAttributeMaxDynamicSharedMemorySize, SMEM_TC);
    cudaFuncSetAttribute(k_node, cudaFuncAttributeMaxDynamicSharedMemorySize, SMEM_ND);

    void* paug; cudaGetSymbolAddress(&paug, g_aug);
    void* pxb;  cudaGetSymbolAddress(&pxb, g_xb);
    float2* XAp = (float2*)paug + 128;
    float2* XBp = (float2*)pxb;

    // 0: init
    k_init<<<(C_TOT + 255) / 256, 256>>>(h0, x0, hout, ei, A_re, A_im, coeffs,
                                         e_w1, e_w2, c_w1, c_w2, enc_w);
    // 1: zero agg
    k_zero_agg<<<(NN * HH + 255) / 256, 256>>>();
    // 2: Newton iter1 T
    k_nt<<<256, 256>>>(XAp, 32768, 256);
    // 3: edge layer 0 — PROFILED SLOT (bf16-mirror LDG gather)
    k_edge_msg<<<TCGRID, 512, SMEM_TC>>>(ei, eattr, e_w1, e_b1, e_b2, 0);
    // 4-8: Newton iters (3 total), ends in XB
    k_nx<<<256, 256>>>(XAp, 32768, 256, XBp, 16384, 128);
    k_nt<<<256, 256>>>(XBp, 16384, 128);
    k_nx<<<256, 256>>>(XBp, 16384, 128, XAp, 32768, 256);
    k_nt<<<256, 256>>>(XAp, 32768, 256);
    k_nx<<<256, 256>>>(XAp, 32768, 256, XBp, 16384, 128);
    // 9-12: rest of quantum precompute
    k_q<<<256, 256>>>(A_re, A_im, XBp, 16384, 128);
    k_b<<<256, 256>>>();
    k_m<<<128, 256>>>();
    k_w<<<128, 256>>>(dec_w);
    // 13: node layer 0
    k_node<<<(NN + 127) / 128, 256, SMEM_ND>>>(hout, enc_b, 0, dec_b);
    // 14: zero agg
    k_zero_agg<<<(NN * HH + 255) / 256, 256>>>();
    // 15: edge layer 1
    k_edge_msg<<<TCGRID, 512, SMEM_TC>>>(ei, eattr, e_w1 + 258 * HH,
                                         e_b1 + HH, e_b2 + HH, 1);
    // 16: node layer 1
    k_node<<<(NN + 127) / 128, 256, SMEM_ND>>>(hout, enc_b + HH, 1, dec_b + HH);
    // 17: final coordinate update
    k_edge_final<<<TCGRID, 512, SMEM_TC>>>(ei, eattr, c_w1, c_b1, c_b2,
                                           c_w3, xout);
}